// round 12
// baseline (speedup 1.0000x reference)
#include <cuda_runtime.h>
#include <cuda_fp16.h>
#include <math.h>
#include <float.h>
#include <stdint.h>

#define NN 256
#define CC 128
#define HH 4
#define DD 32
#define MM (NN*NN)     // 65536
#define HD (HH*DD)     // 128
#define INF_ 1e9f
#define LN_EPS 1e-5f

// ---- scratch (half data stored as uint32 half2 words) ----
__device__ uint32_t g_xn32[MM*CC/2];     // xn half2-packed along C
__device__ uint32_t g_q32 [MM*HD/2];     // q half, scale applied
__device__ uint32_t g_k32 [MM*HD/2];     // k half
__device__ uint32_t g_vt32[MM*HD/2];     // v half, layout [I][h][d][key]
__device__ uint32_t g_g32 [MM*HD/2];     // gate pre-sigmoid, half2
__device__ uint32_t g_o32 [MM*HD/2];     // attn out (normalized), half2
__device__ float    g_tbt[HH*NN*NN];     // [h][j][k]
__device__ uint32_t g_wp32[4*HD*CC/2];   // [wi][n][kp] = half2(W[2kp][n],W[2kp+1][n])
__device__ uint32_t g_wop32[CC*HD/2];    // [n][kp] = half2(wo[n][2kp],wo[n][2kp+1])

// ---------------------------------------------------------------
__device__ __forceinline__ uint32_t pack_h2(float lo, float hi) {
    __half2 h = __floats2half2_rn(lo, hi);
    return *(uint32_t*)&h;
}
__device__ __forceinline__ float2 unpack_h2(uint32_t w) {
    __half2 h = *(__half2*)&w;
    return __half22float2(h);
}

__device__ __forceinline__ void mma_f16(float c[4], const uint32_t a[4],
                                        uint32_t b0, uint32_t b1) {
    asm volatile(
        "mma.sync.aligned.m16n8k16.row.col.f32.f16.f16.f32 "
        "{%0,%1,%2,%3}, {%4,%5,%6,%7}, {%8,%9}, {%0,%1,%2,%3};\n"
        : "+f"(c[0]), "+f"(c[1]), "+f"(c[2]), "+f"(c[3])
        : "r"(a[0]), "r"(a[1]), "r"(a[2]), "r"(a[3]), "r"(b0), "r"(b1));
}

__device__ __forceinline__ void ldsm_x4(uint32_t& r0, uint32_t& r1,
                                        uint32_t& r2, uint32_t& r3, uint32_t addr) {
    asm volatile("ldmatrix.sync.aligned.m8n8.x4.shared.b16 {%0,%1,%2,%3}, [%4];"
                 : "=r"(r0), "=r"(r1), "=r"(r2), "=r"(r3) : "r"(addr));
}

// ---------------------------------------------------------------
// Kernel 0: pack weights to half2 (W^T for q/k/v/g, wo rows for out)
// ---------------------------------------------------------------
__global__ void prep_weights(const float* __restrict__ wq, const float* __restrict__ wk,
                             const float* __restrict__ wv, const float* __restrict__ wg,
                             const float* __restrict__ wo)
{
    int idx = blockIdx.x * 256 + threadIdx.x;
    if (idx < 4*HD*CC/2) {
        int wi = idx >> 13;
        int rem = idx & 8191;
        int n = rem >> 6, kp = rem & 63;
        const float* W = (wi == 0) ? wq : (wi == 1) ? wk : (wi == 2) ? wv : wg;
        g_wp32[idx] = pack_h2(W[(2*kp)*HD + n], W[(2*kp + 1)*HD + n]);
    } else {
        int r = idx - 4*HD*CC/2;
        int n = r >> 6, kp = r & 63;
        g_wop32[r] = pack_h2(wo[n*HD + 2*kp], wo[n*HD + 2*kp + 1]);
    }
}

// ---------------------------------------------------------------
// Kernel 1: LayerNorm (warp per row) + triangle-bias dots
// ---------------------------------------------------------------
__global__ __launch_bounds__(256)
void ln_kernel(const float* __restrict__ x,
               const float* __restrict__ ln_w,
               const float* __restrict__ ln_b,
               const float* __restrict__ w_bias)
{
    int warp = threadIdx.x >> 5, lane = threadIdx.x & 31;
    int m  = blockIdx.x * 8 + warp;
    int i1 = m >> 8;
    int i2 = m & 255;

    float4 v4 = *(const float4*)&x[(i2*NN + i1)*CC + lane*4];

    float s = v4.x + v4.y + v4.z + v4.w;
    #pragma unroll
    for (int o = 16; o > 0; o >>= 1) s += __shfl_xor_sync(0xffffffffu, s, o);
    float mu = s * (1.0f / CC);

    float dx = v4.x - mu, dy = v4.y - mu, dz = v4.z - mu, dw = v4.w - mu;
    float s2 = dx*dx + dy*dy + dz*dz + dw*dw;
    #pragma unroll
    for (int o = 16; o > 0; o >>= 1) s2 += __shfl_xor_sync(0xffffffffu, s2, o);
    float rs = rsqrtf(s2 * (1.0f / CC) + LN_EPS);

    float4 w4 = *(const float4*)&ln_w[lane*4];
    float4 b4 = *(const float4*)&ln_b[lane*4];
    float xn0 = dx*rs*w4.x + b4.x;
    float xn1 = dy*rs*w4.y + b4.y;
    float xn2 = dz*rs*w4.z + b4.z;
    float xn3 = dw*rs*w4.w + b4.w;

    *(uint2*)&g_xn32[m*(CC/2) + lane*2] =
        make_uint2(pack_h2(xn0, xn1), pack_h2(xn2, xn3));

    // triangle bias dots; layout [h][j=i1][k=i2]
    float acc[4];
    #pragma unroll
    for (int h = 0; h < 4; h++) {
        float4 wb = *(const float4*)&w_bias[h*CC + lane*4];
        acc[h] = xn0*wb.x + xn1*wb.y + xn2*wb.z + xn3*wb.w;
    }
    #pragma unroll
    for (int o = 16; o > 0; o >>= 1) {
        #pragma unroll
        for (int h = 0; h < 4; h++)
            acc[h] += __shfl_xor_sync(0xffffffffu, acc[h], o);
    }
    if (lane < 4)
        g_tbt[(lane*NN + i1)*NN + i2] = acc[lane];
}

// ---------------------------------------------------------------
// Kernel 2: q/k/v/g projections, f16 mma m16n8k16, single K pass
// ---------------------------------------------------------------
#define TS_STR 68
#define TS_SZ (128*TS_STR)
#define GEMM_SMEM (2*TS_SZ*4)     // 69632 B

__global__ __launch_bounds__(256, 2)
void gemm_proj_f16()
{
    extern __shared__ uint32_t ts[];
    uint32_t* As = ts;
    uint32_t* Bs = ts + TS_SZ;

    int wi = blockIdx.y;
    int m0 = blockIdx.x * 128;
    float osc = (wi == 0) ? 0.17677669529663689f : 1.0f;

    int tid = threadIdx.x;
    int warp = tid >> 5, lane = tid & 31;
    int g = lane >> 2, t = lane & 3;
    int wm = warp >> 2, wn = warp & 3;
    int mbase = wm*64, nbase = wn*32;

    const uint32_t* wp = g_wp32 + wi*HD*(CC/2);
    #pragma unroll
    for (int i = 0; i < 8; i++) {
        int f = tid + 256*i;
        int r = f >> 4, q4 = (f & 15) * 4;
        *(uint4*)&As[r*TS_STR + q4] = *(const uint4*)&g_xn32[(m0 + r)*(CC/2) + q4];
        *(uint4*)&Bs[r*TS_STR + q4] = *(const uint4*)&wp[r*(CC/2) + q4];
    }
    __syncthreads();

    float acc[4][4][4] = {};

    #pragma unroll
    for (int ks = 0; ks < 8; ks++) {
        uint32_t af[4][4];
        #pragma unroll
        for (int mt = 0; mt < 4; mt++) {
            int r0 = mbase + mt*16 + g;
            af[mt][0] = As[ r0     *TS_STR + ks*8 + t    ];
            af[mt][1] = As[(r0 + 8)*TS_STR + ks*8 + t    ];
            af[mt][2] = As[ r0     *TS_STR + ks*8 + t + 4];
            af[mt][3] = As[(r0 + 8)*TS_STR + ks*8 + t + 4];
        }
        uint32_t bf0[4], bf1[4];
        #pragma unroll
        for (int nt = 0; nt < 4; nt++) {
            int nc = nbase + nt*8 + g;
            bf0[nt] = Bs[nc*TS_STR + ks*8 + t    ];
            bf1[nt] = Bs[nc*TS_STR + ks*8 + t + 4];
        }
        #pragma unroll
        for (int mt = 0; mt < 4; mt++)
            #pragma unroll
            for (int nt = 0; nt < 4; nt++)
                mma_f16(acc[mt][nt], af[mt], bf0[nt], bf1[nt]);
    }

    #pragma unroll
    for (int mt = 0; mt < 4; mt++) {
        int row0 = m0 + mbase + mt*16 + g;
        int row1 = row0 + 8;
        #pragma unroll
        for (int nt = 0; nt < 4; nt++) {
            int ncol = nbase + nt*8 + 2*t;
            float c00 = acc[mt][nt][0]*osc, c01 = acc[mt][nt][1]*osc;
            float c10 = acc[mt][nt][2]*osc, c11 = acc[mt][nt][3]*osc;
            if (wi == 0) {
                g_q32[row0*(HD/2) + (ncol >> 1)] = pack_h2(c00, c01);
                g_q32[row1*(HD/2) + (ncol >> 1)] = pack_h2(c10, c11);
            } else if (wi == 1) {
                g_k32[row0*(HD/2) + (ncol >> 1)] = pack_h2(c00, c01);
                g_k32[row1*(HD/2) + (ncol >> 1)] = pack_h2(c10, c11);
            } else if (wi == 2) {
                __half* vt = (__half*)g_vt32;
                int h = ncol >> 5, d = ncol & 31;
                int I0 = row0 >> 8, key0 = row0 & 255;
                int I1 = row1 >> 8, key1 = row1 & 255;
                vt[((I0*HH + h)*DD + d    )*NN + key0] = __float2half_rn(c00);
                vt[((I0*HH + h)*DD + d + 1)*NN + key0] = __float2half_rn(c01);
                vt[((I1*HH + h)*DD + d    )*NN + key1] = __float2half_rn(c10);
                vt[((I1*HH + h)*DD + d + 1)*NN + key1] = __float2half_rn(c11);
            } else {
                g_g32[row0*(HD/2) + (ncol >> 1)] = pack_h2(c00, c01);
                g_g32[row1*(HD/2) + (ncol >> 1)] = pack_h2(c10, c11);
            }
        }
    }
}

// ---------------------------------------------------------------
// Kernel 3: f16 mma flash attention with ldmatrix fragment loads.
// 8 warps x 32 queries, 32-key chunks, no-max softmax.
// ---------------------------------------------------------------
#define KSH_STR 20
#define VT_STR 132
#define ATTN_SMEM ((NN*KSH_STR + DD*VT_STR + NN) * 4)   // 38400 B

__global__ __launch_bounds__(256, 2)
void attn_f16(const float* __restrict__ mask)
{
    extern __shared__ uint32_t sm32[];
    uint32_t* Ksh = sm32;                       // [256][20]
    uint32_t* Vt  = sm32 + NN*KSH_STR;          // [32][132]
    float*    mb  = (float*)(sm32 + NN*KSH_STR + DD*VT_STR); // [256]

    int I = blockIdx.x, h = blockIdx.y;
    int tid  = threadIdx.x;
    int warp = tid >> 5, lane = tid & 31;
    int g = lane >> 2, t = lane & 3;

    // fill K: [key][16 words]
    #pragma unroll
    for (int i = 0; i < 16; i++) {
        int idx = tid + 256*i;
        int key = idx >> 4, w = idx & 15;
        Ksh[key*KSH_STR + w] = g_k32[(size_t)(I*NN + key)*(HD/2) + h*16 + w];
    }
    // fill Vt: [d][128 words]
    {
        const uint32_t* vsrc = g_vt32 + (size_t)(I*HH + h)*DD*(NN/2);
        #pragma unroll
        for (int i = 0; i < 16; i++) {
            int idx = tid + 256*i;
            int d = idx >> 7, w = idx & 127;
            Vt[d*VT_STR + w] = vsrc[d*(NN/2) + w];
        }
    }
    mb[tid] = INF_ * (mask[tid*NN + I] - 1.0f);

    // resident Q fragments
    int q0 = warp * 32;
    const uint32_t* qbase = g_q32 + (size_t)(I*NN)*(HD/2) + h*16;
    uint32_t aq[2][2][4];
    #pragma unroll
    for (int mt = 0; mt < 2; mt++)
        #pragma unroll
        for (int ks = 0; ks < 2; ks++) {
            int r0 = q0 + mt*16 + g;
            aq[mt][ks][0] = qbase[(size_t) r0     *(HD/2) + ks*8 + t    ];
            aq[mt][ks][1] = qbase[(size_t)(r0 + 8)*(HD/2) + ks*8 + t    ];
            aq[mt][ks][2] = qbase[(size_t) r0     *(HD/2) + ks*8 + t + 4];
            aq[mt][ks][3] = qbase[(size_t)(r0 + 8)*(HD/2) + ks*8 + t + 4];
        }

    // ldmatrix per-lane base addresses
    int sel = lane >> 3;                 // matrix selector 0..3
    uint32_t ksh_u = (uint32_t)__cvta_generic_to_shared(Ksh);
    uint32_t vt_u  = (uint32_t)__cvta_generic_to_shared(Vt);
    // K: mat0/1 = keys +0..7 (b0/b1), mat2/3 = keys +8..15
    uint32_t kaddr = ksh_u + ((((sel >> 1)*8 + (lane & 7))*KSH_STR) + (sel & 1)*4) * 4;
    // V: mat0/1 = d +0..7 (bv0/bv1), mat2/3 = d +8..15
    uint32_t vaddr = vt_u + (((sel >> 1)*8 + (lane & 7))*VT_STR) * 4 + (sel & 1)*16;

    float Of[2][4][4] = {};
    float lacc[2][2] = {};

    const float* tbp = g_tbt + h*NN*NN;

    __syncthreads();

    for (int kc = 0; kc < NN; kc += 32) {
        // ---- S = Q K^T ----
        float S[2][4][4] = {};
        #pragma unroll
        for (int ks = 0; ks < 2; ks++) {
            uint32_t b0[4], b1[4];
            ldsm_x4(b0[0], b1[0], b0[1], b1[1],
                    kaddr + ( kc      *KSH_STR + ks*8) * 4);
            ldsm_x4(b0[2], b1[2], b0[3], b1[3],
                    kaddr + ((kc + 16)*KSH_STR + ks*8) * 4);
            #pragma unroll
            for (int nt = 0; nt < 4; nt++) {
                mma_f16(S[0][nt], aq[0][ks], b0[nt], b1[nt]);
                mma_f16(S[1][nt], aq[1][ks], b0[nt], b1[nt]);
            }
        }
        // ---- biases + exp + row sums ----
        #pragma unroll
        for (int nt = 0; nt < 4; nt++) {
            int kcol = kc + nt*8 + t*2;
            float2 mbv = *(const float2*)&mb[kcol];
            #pragma unroll
            for (int mt = 0; mt < 2; mt++) {
                int row0 = q0 + mt*16 + g;
                float2 t0 = *(const float2*)&tbp[ row0     *NN + kcol];
                float2 t1 = *(const float2*)&tbp[(row0 + 8)*NN + kcol];
                float p0 = __expf(S[mt][nt][0] + mbv.x + t0.x);
                float p1 = __expf(S[mt][nt][1] + mbv.y + t0.y);
                float p2 = __expf(S[mt][nt][2] + mbv.x + t1.x);
                float p3 = __expf(S[mt][nt][3] + mbv.y + t1.y);
                S[mt][nt][0] = p0; S[mt][nt][1] = p1;
                S[mt][nt][2] = p2; S[mt][nt][3] = p3;
                lacc[mt][0] += p0 + p1;
                lacc[mt][1] += p2 + p3;
            }
        }
        // ---- O += P V ----
        #pragma unroll
        for (int kh = 0; kh < 2; kh++) {
            int kcp = (kc >> 1) + kh*8;
            uint32_t bv0[4], bv1[4];
            ldsm_x4(bv0[0], bv1[0], bv0[1], bv1[1], vaddr + kcp*4);
            ldsm_x4(bv0[2], bv1[2], bv0[3], bv1[3], vaddr + (16*VT_STR + kcp)*4);
            #pragma unroll
            for (int mt = 0; mt < 2; mt++) {
                uint32_t ap[4];
                ap[0] = pack_h2(S[mt][kh*2  ][0], S[mt][kh*2  ][1]);
                ap[1] = pack_h2(S[mt][kh*2  ][2], S[mt][kh*2  ][3]);
                ap[2] = pack_h2(S[mt][kh*2+1][0], S[mt][kh*2+1][1]);
                ap[3] = pack_h2(S[mt][kh*2+1][2], S[mt][kh*2+1][3]);
                #pragma unroll
                for (int ntd = 0; ntd < 4; ntd++)
                    mma_f16(Of[mt][ntd], ap, bv0[ntd], bv1[ntd]);
            }
        }
    }

    // ---- epilogue: normalize, store half2 ----
    uint32_t* obase = g_o32 + (size_t)(I*NN)*(HD/2) + h*16;
    #pragma unroll
    for (int mt = 0; mt < 2; mt++) {
        float l0 = lacc[mt][0];
        l0 += __shfl_xor_sync(0xffffffffu, l0, 1);
        l0 += __shfl_xor_sync(0xffffffffu, l0, 2);
        float l1 = lacc[mt][1];
        l1 += __shfl_xor_sync(0xffffffffu, l1, 1);
        l1 += __shfl_xor_sync(0xffffffffu, l1, 2);
        float inv0 = 1.0f / l0;
        float inv1 = 1.0f / l1;
        int row0 = q0 + mt*16 + g;
        int row1 = row0 + 8;
        #pragma unroll
        for (int ntd = 0; ntd < 4; ntd++) {
            int wp = ntd*4 + t;          // (col = ntd*8 + 2t) >> 1
            obase[(size_t)row0*(HD/2) + wp] = pack_h2(Of[mt][ntd][0]*inv0, Of[mt][ntd][1]*inv0);
            obase[(size_t)row1*(HD/2) + wp] = pack_h2(Of[mt][ntd][2]*inv1, Of[mt][ntd][3]*inv1);
        }
    }
}

// ---------------------------------------------------------------
// Kernel 4: gated output projection, f16 mma + scatter epilogue
// ---------------------------------------------------------------
__global__ __launch_bounds__(256, 2)
void gemm_out_f16(const float* __restrict__ bg, const float* __restrict__ bo,
                  float* __restrict__ out)
{
    extern __shared__ uint32_t ts[];
    uint32_t* As = ts;
    uint32_t* Bs = ts + TS_SZ;

    int m0 = blockIdx.x * 128;

    int tid = threadIdx.x;
    int warp = tid >> 5, lane = tid & 31;
    int g = lane >> 2, t = lane & 3;
    int wm = warp >> 2, wn = warp & 3;
    int mbase = wm*64, nbase = wn*32;

    // A: load o/g half2, gate, repack; B: copy packed wo
    #pragma unroll
    for (int i = 0; i < 16; i++) {
        int s = tid + 256*i;                    // 0..4095
        int r = s >> 5, wp = (s & 31) * 2;      // 2 words = 4 halves
        uint2 o2 = *(const uint2*)&g_o32[(size_t)(m0 + r)*(HD/2) + wp];
        uint2 g2 = *(const uint2*)&g_g32[(size_t)(m0 + r)*(HD/2) + wp];
        float4 bg4 = *(const float4*)&bg[wp*2];
        float2 oa = unpack_h2(o2.x), ob = unpack_h2(o2.y);
        float2 ga = unpack_h2(g2.x), gb = unpack_h2(g2.y);
        float a0 = oa.x / (1.0f + __expf(-(ga.x + bg4.x)));
        float a1 = oa.y / (1.0f + __expf(-(ga.y + bg4.y)));
        float a2 = ob.x / (1.0f + __expf(-(gb.x + bg4.z)));
        float a3 = ob.y / (1.0f + __expf(-(gb.y + bg4.w)));
        As[r*TS_STR + wp    ] = pack_h2(a0, a1);
        As[r*TS_STR + wp + 1] = pack_h2(a2, a3);
    }
    #pragma unroll
    for (int i = 0; i < 8; i++) {
        int f = tid + 256*i;
        int n = f >> 4, kp4 = (f & 15) * 4;
        *(uint4*)&Bs[n*TS_STR + kp4] = *(const uint4*)&g_wop32[n*(HD/2) + kp4];
    }
    __syncthreads();

    float acc[4][4][4] = {};

    #pragma unroll
    for (int ks = 0; ks < 8; ks++) {
        uint32_t af[4][4];
        #pragma unroll
        for (int mt = 0; mt < 4; mt++) {
            int r0 = mbase + mt*16 + g;
            af[mt][0] = As[ r0     *TS_STR + ks*8 + t    ];
            af[mt][1] = As[(r0 + 8)*TS_STR + ks*8 + t    ];
            af[mt][2] = As[ r0     *TS_STR + ks*8 + t + 4];
            af[mt][3] = As[(r0 + 8)*TS_STR + ks*8 + t + 4];
        }
        uint32_t bf0[4], bf1[4];
        #pragma unroll
        for (int nt = 0; nt < 4; nt++) {
            int nc = nbase + nt*8 + g;
            bf0[nt] = Bs[nc*TS_STR + ks*8 + t    ];
            bf1[nt] = Bs[nc*TS_STR + ks*8 + t + 4];
        }
        #pragma unroll
        for (int mt = 0; mt < 4; mt++)
            #pragma unroll
            for (int nt = 0; nt < 4; nt++)
                mma_f16(acc[mt][nt], af[mt], bf0[nt], bf1[nt]);
    }

    #pragma unroll
    for (int mt = 0; mt < 4; mt++) {
        int mr0 = m0 + mbase + mt*16 + g;
        int mr1 = mr0 + 8;
        int or0 = (mr0 & 255)*NN + (mr0 >> 8);   // swapaxes scatter
        int or1 = (mr1 & 255)*NN + (mr1 >> 8);
        #pragma unroll
        for (int nt = 0; nt < 4; nt++) {
            int col = nbase + nt*8 + 2*t;
            float2 b2 = *(const float2*)&bo[col];
            float2 w0 = make_float2(acc[mt][nt][0] + b2.x, acc[mt][nt][1] + b2.y);
            float2 w1 = make_float2(acc[mt][nt][2] + b2.x, acc[mt][nt][3] + b2.y);
            *(float2*)&out[or0*CC + col] = w0;
            *(float2*)&out[or1*CC + col] = w1;
        }
    }
}

// ---------------------------------------------------------------
extern "C" void kernel_launch(void* const* d_in, const int* in_sizes, int n_in,
                              void* d_out, int out_size)
{
    const float* x      = (const float*)d_in[0];
    const float* mask   = (const float*)d_in[1];
    const float* ln_w   = (const float*)d_in[2];
    const float* ln_b   = (const float*)d_in[3];
    const float* w_bias = (const float*)d_in[4];
    const float* wq     = (const float*)d_in[5];
    const float* wk     = (const float*)d_in[6];
    const float* wv     = (const float*)d_in[7];
    const float* wg     = (const float*)d_in[8];
    const float* bg     = (const float*)d_in[9];
    const float* wo     = (const float*)d_in[10];
    const float* bo     = (const float*)d_in[11];
    float* out = (float*)d_out;

    static bool attr_set = false;
    if (!attr_set) {
        cudaFuncSetAttribute(attn_f16, cudaFuncAttributeMaxDynamicSharedMemorySize,
                             ATTN_SMEM);
        cudaFuncSetAttribute(gemm_proj_f16, cudaFuncAttributeMaxDynamicSharedMemorySize,
                             GEMM_SMEM);
        cudaFuncSetAttribute(gemm_out_f16, cudaFuncAttributeMaxDynamicSharedMemorySize,
                             GEMM_SMEM);
        attr_set = true;
    }

    prep_weights<<<160, 256>>>(wq, wk, wv, wg, wo);
    ln_kernel<<<MM/8, 256>>>(x, ln_w, ln_b, w_bias);
    gemm_proj_f16<<<dim3(MM/128, 4), 256, GEMM_SMEM>>>();
    attn_f16<<<dim3(NN, HH), 256, ATTN_SMEM>>>(mask);
    gemm_out_f16<<<dim3(MM/128, 1), 256, GEMM_SMEM>>>(bg, bo, out);
}